// round 12
// baseline (speedup 1.0000x reference)
#include <cuda_runtime.h>
#include <cuda_bf16.h>
#include <math.h>

#define E    512
#define HH   1536
#define G4   6144
#define SS   32
#define TT   48
#define NV   128
#define NB   256       // persistent blocks, 2/SM guaranteed by launch_bounds
#define NT   384       // 12 warps
#define UPB  6         // h2/c2 units per block
#define RPB  24        // gate rows / whh1 rows per block
#define KU   4         // h-vector elems per thread (HH/NT)
#define LSTR 64        // logit slot stride (256B)
#define FSTR 32        // flag slot stride (128B)
#define WELEM (G4 * HH)

// ---------------- persistent device state ----------------
__device__ float          g_xproj[NV * G4];            // W_ih1@emb[v] + b_ih1 + b_hh1
__device__ __nv_bfloat16  g_w2cat[(size_t)G4 * 2 * HH];// [W_ih2 | W_hh2] rows of 3072
__device__ __nv_bfloat16  g_whh1[WELEM];
__device__ float          g_c1[2][HH];
__device__ float          g_c2[HH];
__device__ float          g_h2[2][HH];
__device__ float          g_g1[2][G4];                 // W_hh1 @ h1(t), double buffered
__device__ float          g_log3[3][SS * LSTR];        // triple-buffered padded logits
__device__ unsigned       g_flags[NB * FSTR];          // monotonic epochs (never reset)

__device__ __forceinline__ float fsigm(float x) {
    return __fdividef(1.0f, 1.0f + __expf(-x));
}
__device__ __forceinline__ float ftanh(float x) {
    x = fminf(fmaxf(x, -15.0f), 15.0f);
    float e = __expf(2.0f * x);
    return __fdividef(e - 1.0f, e + 1.0f);
}
__device__ __forceinline__ float warpsum(float v) {
    #pragma unroll
    for (int o = 16; o; o >>= 1) v += __shfl_down_sync(0xffffffffu, v, o);
    return v;
}

// 2 rows from one base, vector from smem; accumulate (no init)
template<int SEGS>
__device__ __forceinline__ void dot2_acc(const __nv_bfloat16* __restrict__ base,
                                         size_t stride, const float* __restrict__ sv,
                                         int lane, float* acc) {
    #pragma unroll
    for (int j = 0; j < SEGS; j++) {
        int seg = lane + 32 * j;
        const float4* v = (const float4*)(sv + seg * 8);
        float4 v0 = v[0], v1 = v[1];
        #pragma unroll
        for (int r = 0; r < 2; r++) {
            uint4 a = __ldg((const uint4*)(base + r * stride) + seg);
            float2 p;
            p = __bfloat1622float2(*(const __nv_bfloat162*)&a.x);
            acc[r] = fmaf(p.x, v0.x, acc[r]); acc[r] = fmaf(p.y, v0.y, acc[r]);
            p = __bfloat1622float2(*(const __nv_bfloat162*)&a.y);
            acc[r] = fmaf(p.x, v0.z, acc[r]); acc[r] = fmaf(p.y, v0.w, acc[r]);
            p = __bfloat1622float2(*(const __nv_bfloat162*)&a.z);
            acc[r] = fmaf(p.x, v1.x, acc[r]); acc[r] = fmaf(p.y, v1.y, acc[r]);
            p = __bfloat1622float2(*(const __nv_bfloat162*)&a.w);
            acc[r] = fmaf(p.x, v1.z, acc[r]); acc[r] = fmaf(p.y, v1.w, acc[r]);
        }
    }
}

// FUSED: 2 rows from baseA + 2 rows from baseB, ONE vector pass
template<int SEGS>
__device__ __forceinline__ void dot2x2_acc(const __nv_bfloat16* __restrict__ baseA,
                                           size_t strideA,
                                           const __nv_bfloat16* __restrict__ baseB,
                                           size_t strideB,
                                           const float* __restrict__ sv, int lane,
                                           float* accA, float* accB) {
    #pragma unroll
    for (int j = 0; j < SEGS; j++) {
        int seg = lane + 32 * j;
        const float4* v = (const float4*)(sv + seg * 8);
        float4 v0 = v[0], v1 = v[1];
        uint4 a0 = __ldg((const uint4*)(baseA) + seg);
        uint4 a1 = __ldg((const uint4*)(baseA + strideA) + seg);
        uint4 b0 = __ldg((const uint4*)(baseB) + seg);
        uint4 b1 = __ldg((const uint4*)(baseB + strideB) + seg);
        float2 p;
        #define ACC8(acc, q) \
            p = __bfloat1622float2(*(const __nv_bfloat162*)&q.x); \
            acc = fmaf(p.x, v0.x, acc); acc = fmaf(p.y, v0.y, acc); \
            p = __bfloat1622float2(*(const __nv_bfloat162*)&q.y); \
            acc = fmaf(p.x, v0.z, acc); acc = fmaf(p.y, v0.w, acc); \
            p = __bfloat1622float2(*(const __nv_bfloat162*)&q.z); \
            acc = fmaf(p.x, v1.x, acc); acc = fmaf(p.y, v1.y, acc); \
            p = __bfloat1622float2(*(const __nv_bfloat162*)&q.w); \
            acc = fmaf(p.x, v1.z, acc); acc = fmaf(p.y, v1.w, acc);
        ACC8(accA[0], a0)
        ACC8(accA[1], a1)
        ACC8(accB[0], b0)
        ACC8(accB[1], b1)
        #undef ACC8
    }
}

// symmetric grid barrier: padded per-block flags, first NB threads poll
__device__ __forceinline__ void grid_sync(int b, unsigned ep) {
    __threadfence();
    __syncthreads();
    if (threadIdx.x == 0)
        *(volatile unsigned*)&g_flags[b * FSTR] = ep;
    if (threadIdx.x < NB) {
        volatile unsigned* f = &g_flags[threadIdx.x * FSTR];
        while ((int)(*f - ep) < 0) { __nanosleep(64); }
    }
    __syncthreads();
    __threadfence();
}

// ================== the one and only kernel ==================
__global__ void __launch_bounds__(NT, 2)
nas_all(const int*   __restrict__ input_id,
        const float* __restrict__ emb,
        const float* __restrict__ Wih1,
        const float* __restrict__ Whh1f,
        const float* __restrict__ bih1, const float* __restrict__ bhh1,
        const float* __restrict__ Wih2f,
        const float* __restrict__ Whh2f,
        const float* __restrict__ bih2, const float* __restrict__ bhh2,
        const float* __restrict__ Wout,
        const float* __restrict__ bout,
        float* __restrict__ out) {
    __shared__ __align__(16) float sMem[16 * (E + 8)];   // 33.3 KB (prologue); aliased
    float* sV  = sMem;                        // loop: [h1 ; h2] (3072)
    float* sWo = sMem + 2 * HH;               // loop: head slice (192)
    float* sG  = sMem + 2 * HH + SS * UPB;    // loop: gates (24 rows -> 24)
    __shared__ unsigned sBase;

    const int tid  = threadIdx.x;
    const int w    = tid >> 5;
    const int lane = tid & 31;
    const int b    = blockIdx.x;
    const int u0   = b * UPB;

    // warp row assignments (rows-per-warp = 2; never crosses a gate boundary)
    const int l0   = 2 * w;                   // 0..22
    const int gate = l0 / UPB;
    const int j0   = l0 % UPB;
    const int grow = gate * HH + u0 + j0;
    const __nv_bfloat16* w2base = g_w2cat + (size_t)grow * (2 * HH);
    const int r1row = b * RPB + l0;
    const __nv_bfloat16* w1base = g_whh1 + (size_t)r1row * HH;
    const float bsum0 = __ldg(&bih2[grow])     + __ldg(&bhh2[grow]);
    const float bsum1 = __ldg(&bih2[grow + 1]) + __ldg(&bhh2[grow + 1]);

    // ---- epoch base (flags monotonic across graph replays) ----
    if (tid == 0) sBase = g_flags[b * FSTR];
    __syncthreads();
    const unsigned base = sBase;

    // ======== PROLOGUE (distributed by block) ========
    if (tid < UPB) { g_c2[u0 + tid] = 0.f; g_h2[0][u0 + tid] = 0.f; }

    // bf16-convert own RPB rows of W_ih2 / W_hh2 (into concat) and W_hh1
    {
        const size_t r0 = (size_t)b * RPB;
        #pragma unroll
        for (int m = 0; m < 3; m++) {
            const float* src = (m == 0) ? Wih2f : (m == 1) ? Whh2f : Whh1f;
            for (int idx = tid; idx < RPB * HH / 8; idx += NT) {
                size_t e = (size_t)idx * 8;
                size_t row = r0 + e / HH, col = e % HH;
                const float* s = src + row * HH + col;
                float4 a = *(const float4*)s;
                float4 c = *(const float4*)(s + 4);
                __nv_bfloat162 q0 = __floats2bfloat162_rn(a.x, a.y);
                __nv_bfloat162 q1 = __floats2bfloat162_rn(a.z, a.w);
                __nv_bfloat162 q2 = __floats2bfloat162_rn(c.x, c.y);
                __nv_bfloat162 q3 = __floats2bfloat162_rn(c.z, c.w);
                uint4 o;
                o.x = *(unsigned*)&q0; o.y = *(unsigned*)&q1;
                o.z = *(unsigned*)&q2; o.w = *(unsigned*)&q3;
                __nv_bfloat16* d = (m == 2)
                    ? (g_whh1 + row * HH + col)
                    : (g_w2cat + row * (2 * HH) + (m == 1 ? HH : 0) + col);
                *(uint4*)d = o;
            }
        }
    }

    // xproj: own rows r, r+1 (per warp) for all 128 embeddings
    {
        const int r = b * RPB + w * 2;
        float4 Wa[4], Wb[4];
        const float4* wra = (const float4*)(Wih1 + (size_t)r * E);
        const float4* wrb = (const float4*)(Wih1 + (size_t)(r + 1) * E);
        #pragma unroll
        for (int i = 0; i < 4; i++) {
            Wa[i] = __ldg(&wra[lane * 4 + i]);
            Wb[i] = __ldg(&wrb[lane * 4 + i]);
        }
        const float bs0 = __ldg(&bih1[r])     + __ldg(&bhh1[r]);
        const float bs1 = __ldg(&bih1[r + 1]) + __ldg(&bhh1[r + 1]);

        for (int c = 0; c < NV / 16; c++) {
            __syncthreads();
            for (int idx = tid; idx < 16 * (E / 4); idx += NT) {
                int v = idx >> 7, e4 = idx & 127;
                float4 d = __ldg((const float4*)(emb + (size_t)(c * 16 + v) * E) + e4);
                *(float4*)&sMem[v * (E + 8) + e4 * 4] = d;
            }
            __syncthreads();
            #pragma unroll 2
            for (int v = 0; v < 16; v++) {
                const float* ev = &sMem[v * (E + 8) + lane * 16];
                float a0 = 0.f, a1 = 0.f;
                #pragma unroll
                for (int i = 0; i < 4; i++) {
                    float4 x = *(const float4*)(ev + 4 * i);
                    a0 = fmaf(Wa[i].x, x.x, a0); a0 = fmaf(Wa[i].y, x.y, a0);
                    a0 = fmaf(Wa[i].z, x.z, a0); a0 = fmaf(Wa[i].w, x.w, a0);
                    a1 = fmaf(Wb[i].x, x.x, a1); a1 = fmaf(Wb[i].y, x.y, a1);
                    a1 = fmaf(Wb[i].z, x.z, a1); a1 = fmaf(Wb[i].w, x.w, a1);
                }
                a0 = warpsum(a0);
                a1 = warpsum(a1);
                if (lane == 0) {
                    g_xproj[(size_t)(c * 16 + v) * G4 + r]     = a0 + bs0;
                    g_xproj[(size_t)(c * 16 + v) * G4 + r + 1] = a1 + bs1;
                }
            }
        }
    }

    grid_sync(b, base + 1);

    // ======== 48-step controller loop ========
    for (int t = 0; t < TT; t++) {
        const int par = t & 1;
        const int rb = t % 3, wb = (t + 1) % 3, zb = (t + 2) % 3;

        // ---- loads (all argmax-independent) ----
        float lg = 0.f;
        if (t > 0) lg = g_log3[rb][lane * LSTR] + bout[(t - 1) * SS + lane];
        float a0[KU], a1[KU], a2[KU], a3[KU], cc[KU];
        #pragma unroll
        for (int k = 0; k < KU; k++) {
            int u = tid + k * NT;
            sV[HH + u] = g_h2[par][u];          // stage h2(t-1)
            if (t > 0) {
                a0[k] = g_g1[par][u];          a1[k] = g_g1[par][HH + u];
                a2[k] = g_g1[par][2 * HH + u]; a3[k] = g_g1[par][3 * HH + u];
                cc[k] = g_c1[par][u];
            }
        }
        if (tid < SS * UPB) {   // fp32 head slice for this block's units
            int s = tid / UPB, j = tid % UPB;
            sWo[tid] = __ldg(&Wout[((size_t)t * SS + s) * HH + u0 + j]);
        }
        __syncthreads();

        // ---- dotA: W_hh2 @ h2(t-1); loads fly while softmax (shfl-only) runs
        float acc[2] = {0.f, 0.f};
        dot2_acc<6>(w2base + HH, 2 * HH, sV + HH, lane, acc);

        // ---- per-warp redundant softmax/argmax of step t-1 (fused max+argmax)
        int sid = 0;
        if (t > 0) {
            float v = lg;
            float bv = v; int bi = lane;
            #pragma unroll
            for (int o = 16; o; o >>= 1) {
                float ov = __shfl_xor_sync(0xffffffffu, bv, o);
                int   oi = __shfl_xor_sync(0xffffffffu, bi, o);
                if (ov > bv || (ov == bv && oi < bi)) { bv = ov; bi = oi; }
            }
            float e = expf(v - bv), se = e;
            #pragma unroll
            for (int o = 16; o; o >>= 1) se += __shfl_xor_sync(0xffffffffu, se, o);
            float lse = bv + logf(se);
            if (b == 0 && w == 0) out[(t - 1) * SS + lane] = v - lse;
            sid = ((t - 1) & 3) * SS + bi;
        }

        // ---- build h1(t) redundantly; own c1 slice ----
        if (t == 0) {
            int id0 = *input_id;
            const float* xp = g_xproj + (size_t)id0 * G4;
            #pragma unroll
            for (int k = 0; k < KU; k++) {
                int u = tid + k * NT;
                float gi = xp[u], gg = xp[2 * HH + u], go = xp[3 * HH + u];
                float cn = fsigm(gi) * ftanh(gg);
                sV[u] = fsigm(go) * ftanh(cn);
                if (u >= u0 && u < u0 + UPB) g_c1[1][u] = cn;
            }
        } else {
            const float* xp = g_xproj + (size_t)sid * G4;
            #pragma unroll
            for (int k = 0; k < KU; k++) {
                int u = tid + k * NT;
                float gi = a0[k] + xp[u];
                float gf = a1[k] + xp[HH + u];
                float gg = a2[k] + xp[2 * HH + u];
                float go = a3[k] + xp[3 * HH + u];
                float cn = fsigm(gf) * cc[k] + fsigm(gi) * ftanh(gg);
                sV[u] = fsigm(go) * ftanh(cn);
                if (u >= u0 && u < u0 + UPB) g_c1[par ^ 1][u] = cn;
            }
        }
        __syncthreads();

        // ---- FUSED dotB: W_ih2 rows + W_hh1 rows, one pass over h1(t) ----
        float r1[2] = {0.f, 0.f};
        dot2x2_acc<6>(w2base, 2 * HH, w1base, HH, sV, lane, acc, r1);
        acc[0] = warpsum(acc[0]);
        acc[1] = warpsum(acc[1]);
        r1[0]  = warpsum(r1[0]);
        r1[1]  = warpsum(r1[1]);
        if (lane == 0) {
            sG[l0]     = acc[0] + bsum0;
            sG[l0 + 1] = acc[1] + bsum1;
            g_g1[par ^ 1][r1row]     = r1[0];
            g_g1[par ^ 1][r1row + 1] = r1[1];
        }
        __syncthreads();

        // ---- finalize own h2 units + partial logits -> spread atomics ----
        if (w == 0) {
            float hn = 0.f;
            if (lane < UPB) {
                int u = u0 + lane;
                float gi = sG[lane],           gf = sG[UPB + lane];
                float gg = sG[2 * UPB + lane], go = sG[3 * UPB + lane];
                float c  = g_c2[u];
                float cn = fsigm(gf) * c + fsigm(gi) * ftanh(gg);
                g_c2[u]          = cn;
                hn               = fsigm(go) * ftanh(cn);
                g_h2[par ^ 1][u] = hn;
            }
            float p = 0.f;
            #pragma unroll
            for (int j = 0; j < UPB; j++) {
                float hj = __shfl_sync(0xffffffffu, hn, j);
                p = fmaf(sWo[lane * UPB + j], hj, p);
            }
            atomicAdd(&g_log3[wb][lane * LSTR], p);
        }
        if (b == 0 && w == 1) g_log3[zb][lane * LSTR] = 0.0f;  // recycle buffer

        grid_sync(b, base + 2 + (unsigned)t);
    }

    // epilogue: logp(47) from g_log3[48%3 = 0]
    if (b == 0 && w == 0) {
        float v = g_log3[0][lane * LSTR] + bout[47 * SS + lane];
        float m = v;
        #pragma unroll
        for (int o = 16; o; o >>= 1) m = fmaxf(m, __shfl_xor_sync(0xffffffffu, m, o));
        float e = expf(v - m), se = e;
        #pragma unroll
        for (int o = 16; o; o >>= 1) se += __shfl_xor_sync(0xffffffffu, se, o);
        float lse = m + logf(se);
        out[47 * SS + lane] = v - lse;
    }
}

extern "C" void kernel_launch(void* const* d_in, const int* in_sizes, int n_in,
                              void* d_out, int out_size) {
    const int*   input_id = (const int*)  d_in[0];
    const float* emb      = (const float*)d_in[1];
    const float* W_ih1    = (const float*)d_in[2];
    const float* W_hh1    = (const float*)d_in[3];
    const float* b_ih1    = (const float*)d_in[4];
    const float* b_hh1    = (const float*)d_in[5];
    const float* W_ih2    = (const float*)d_in[6];
    const float* W_hh2    = (const float*)d_in[7];
    const float* b_ih2    = (const float*)d_in[8];
    const float* b_hh2    = (const float*)d_in[9];
    const float* W_out    = (const float*)d_in[10];
    const float* b_out    = (const float*)d_in[11];
    float* out = (float*)d_out;

    nas_all<<<NB, NT>>>(input_id, emb, W_ih1, W_hh1, b_ih1, b_hh1,
                        W_ih2, W_hh2, b_ih2, b_hh2, W_out, b_out, out);
}

// round 13
// speedup vs baseline: 1.0953x; 1.0953x over previous
#include <cuda_runtime.h>
#include <cuda_bf16.h>
#include <math.h>

#define E    512
#define HH   1536
#define G4   6144
#define SS   32
#define TT   48
#define NV   128
#define NB   128       // persistent blocks (1/SM)
#define NT   768       // 24 warps
#define UPB  12        // h2/c2 units per block
#define RPB  48        // gate rows / whh1 rows per block
#define KU   2         // h-vector elems per thread (HH/NT)
#define LSTR 64        // logit slot stride (256B)
#define FSTR 32        // flag slot stride (128B)
#define WELEM (G4 * HH)

typedef unsigned long long u64;

// ---------------- persistent device state ----------------
__device__ float          g_xproj[NV * G4];            // W_ih1@emb[v] + b_ih1 + b_hh1
__device__ __nv_bfloat16  g_w2cat[(size_t)G4 * 2 * HH];// [W_ih2 | W_hh2] rows of 3072
__device__ __nv_bfloat16  g_whh1[WELEM];
__device__ float          g_c1[2][HH];
__device__ float          g_c2[HH];
__device__ float          g_h2[2][HH];
__device__ float          g_g1[2][G4];                 // W_hh1 @ h1(t), double buffered
__device__ float          g_log3[3][SS * LSTR];        // triple-buffered padded logits
__device__ unsigned       g_flags[NB * FSTR];          // monotonic epochs (never reset)

__device__ __forceinline__ float fsigm(float x) {
    return __fdividef(1.0f, 1.0f + __expf(-x));
}
__device__ __forceinline__ float ftanh(float x) {
    x = fminf(fmaxf(x, -15.0f), 15.0f);
    float e = __expf(2.0f * x);
    return __fdividef(e - 1.0f, e + 1.0f);
}
__device__ __forceinline__ float warpsum(float v) {
    #pragma unroll
    for (int o = 16; o; o >>= 1) v += __shfl_down_sync(0xffffffffu, v, o);
    return v;
}

// ---- packed f32x2 helpers (sm_100+) ----
__device__ __forceinline__ u64 f2pack(float x, float y) {
    u64 r; asm("mov.b64 %0, {%1, %2};" : "=l"(r) : "f"(x), "f"(y)); return r;
}
__device__ __forceinline__ float f2sum(u64 v) {
    float x, y; asm("mov.b64 {%0, %1}, %2;" : "=f"(x), "=f"(y) : "l"(v));
    return x + y;
}
__device__ __forceinline__ u64 bf2f2(unsigned q) {   // bf16x2 -> (f32,f32)
    unsigned lo = q << 16, hi = q & 0xFFFF0000u;
    u64 r; asm("mov.b64 %0, {%1, %2};" : "=l"(r) : "r"(lo), "r"(hi)); return r;
}
__device__ __forceinline__ u64 ffma2(u64 a, u64 b, u64 c) {
    u64 d; asm("fma.rn.f32x2 %0, %1, %2, %3;" : "=l"(d) : "l"(a), "l"(b), "l"(c));
    return d;
}

// 2 rows from one base, vector from smem; accumulate (packed f32x2)
template<int SEGS>
__device__ __forceinline__ void dot2_acc(const __nv_bfloat16* __restrict__ base,
                                         size_t stride, const float* __restrict__ sv,
                                         int lane, float* acc) {
    u64 p0 = 0ull, p1 = 0ull;
    #pragma unroll
    for (int j = 0; j < SEGS; j++) {
        int seg = lane + 32 * j;
        const float4* v = (const float4*)(sv + seg * 8);
        float4 v0 = v[0], v1 = v[1];
        u64 vx = f2pack(v0.x, v0.y), vy = f2pack(v0.z, v0.w);
        u64 vz = f2pack(v1.x, v1.y), vw = f2pack(v1.z, v1.w);
        uint4 a = __ldg((const uint4*)base + seg);
        uint4 b = __ldg((const uint4*)(base + stride) + seg);
        p0 = ffma2(bf2f2(a.x), vx, p0); p0 = ffma2(bf2f2(a.y), vy, p0);
        p0 = ffma2(bf2f2(a.z), vz, p0); p0 = ffma2(bf2f2(a.w), vw, p0);
        p1 = ffma2(bf2f2(b.x), vx, p1); p1 = ffma2(bf2f2(b.y), vy, p1);
        p1 = ffma2(bf2f2(b.z), vz, p1); p1 = ffma2(bf2f2(b.w), vw, p1);
    }
    acc[0] += f2sum(p0);
    acc[1] += f2sum(p1);
}

// FUSED: 2 rows from baseA + 2 rows from baseB, ONE vector pass (packed)
template<int SEGS>
__device__ __forceinline__ void dot2x2_acc(const __nv_bfloat16* __restrict__ baseA,
                                           size_t strideA,
                                           const __nv_bfloat16* __restrict__ baseB,
                                           size_t strideB,
                                           const float* __restrict__ sv, int lane,
                                           float* accA, float* accB) {
    u64 pa0 = 0ull, pa1 = 0ull, pb0 = 0ull, pb1 = 0ull;
    #pragma unroll
    for (int j = 0; j < SEGS; j++) {
        int seg = lane + 32 * j;
        const float4* v = (const float4*)(sv + seg * 8);
        float4 v0 = v[0], v1 = v[1];
        u64 vx = f2pack(v0.x, v0.y), vy = f2pack(v0.z, v0.w);
        u64 vz = f2pack(v1.x, v1.y), vw = f2pack(v1.z, v1.w);
        uint4 a0 = __ldg((const uint4*)(baseA) + seg);
        uint4 a1 = __ldg((const uint4*)(baseA + strideA) + seg);
        uint4 b0 = __ldg((const uint4*)(baseB) + seg);
        uint4 b1 = __ldg((const uint4*)(baseB + strideB) + seg);
        pa0 = ffma2(bf2f2(a0.x), vx, pa0); pa0 = ffma2(bf2f2(a0.y), vy, pa0);
        pa0 = ffma2(bf2f2(a0.z), vz, pa0); pa0 = ffma2(bf2f2(a0.w), vw, pa0);
        pa1 = ffma2(bf2f2(a1.x), vx, pa1); pa1 = ffma2(bf2f2(a1.y), vy, pa1);
        pa1 = ffma2(bf2f2(a1.z), vz, pa1); pa1 = ffma2(bf2f2(a1.w), vw, pa1);
        pb0 = ffma2(bf2f2(b0.x), vx, pb0); pb0 = ffma2(bf2f2(b0.y), vy, pb0);
        pb0 = ffma2(bf2f2(b0.z), vz, pb0); pb0 = ffma2(bf2f2(b0.w), vw, pb0);
        pb1 = ffma2(bf2f2(b1.x), vx, pb1); pb1 = ffma2(bf2f2(b1.y), vy, pb1);
        pb1 = ffma2(bf2f2(b1.z), vz, pb1); pb1 = ffma2(bf2f2(b1.w), vw, pb1);
    }
    accA[0] += f2sum(pa0);
    accA[1] += f2sum(pa1);
    accB[0] += f2sum(pb0);
    accB[1] += f2sum(pb1);
}

// symmetric grid barrier: padded per-block flags, first NB threads poll
__device__ __forceinline__ void grid_sync(int b, unsigned ep) {
    __threadfence();
    __syncthreads();
    if (threadIdx.x == 0)
        *(volatile unsigned*)&g_flags[b * FSTR] = ep;
    if (threadIdx.x < NB) {
        volatile unsigned* f = &g_flags[threadIdx.x * FSTR];
        while ((int)(*f - ep) < 0) { __nanosleep(64); }
    }
    __syncthreads();
    __threadfence();
}

// ================== the one and only kernel ==================
__global__ void __launch_bounds__(NT, 1)
nas_all(const int*   __restrict__ input_id,
        const float* __restrict__ emb,
        const float* __restrict__ Wih1,
        const float* __restrict__ Whh1f,
        const float* __restrict__ bih1, const float* __restrict__ bhh1,
        const float* __restrict__ Wih2f,
        const float* __restrict__ Whh2f,
        const float* __restrict__ bih2, const float* __restrict__ bhh2,
        const float* __restrict__ Wout,
        const float* __restrict__ bout,
        float* __restrict__ out) {
    __shared__ __align__(16) float sMem[16 * (E + 8)];   // 33.3 KB; aliased
    float* sV  = sMem;                        // loop: [h1 ; h2] (3072)
    float* sWo = sMem + 2 * HH;               // loop: head slice (384)
    float* sG  = sMem + 2 * HH + SS * UPB;    // loop: gates (48)
    __shared__ unsigned sBase;

    const int tid  = threadIdx.x;
    const int w    = tid >> 5;
    const int lane = tid & 31;
    const int b    = blockIdx.x;
    const int u0   = b * UPB;

    // warp row assignments (2 rows/warp; never crosses a gate boundary)
    const int l0   = 2 * w;
    const int gate = l0 / UPB;
    const int j0   = l0 % UPB;
    const int grow = gate * HH + u0 + j0;
    const __nv_bfloat16* w2base = g_w2cat + (size_t)grow * (2 * HH);
    const int r1row = b * RPB + l0;
    const __nv_bfloat16* w1base = g_whh1 + (size_t)r1row * HH;
    const float bsum0 = __ldg(&bih2[grow])     + __ldg(&bhh2[grow]);
    const float bsum1 = __ldg(&bih2[grow + 1]) + __ldg(&bhh2[grow + 1]);

    // ---- epoch base (flags monotonic across graph replays) ----
    if (tid == 0) sBase = g_flags[b * FSTR];
    __syncthreads();
    const unsigned base = sBase;

    // ======== PROLOGUE (distributed by block) ========
    if (tid < UPB) { g_c2[u0 + tid] = 0.f; g_h2[0][u0 + tid] = 0.f; }

    // bf16-convert own RPB rows of W_ih2 / W_hh2 (into concat) and W_hh1
    {
        const size_t r0 = (size_t)b * RPB;
        #pragma unroll
        for (int m = 0; m < 3; m++) {
            const float* src = (m == 0) ? Wih2f : (m == 1) ? Whh2f : Whh1f;
            for (int idx = tid; idx < RPB * HH / 8; idx += NT) {
                size_t e = (size_t)idx * 8;
                size_t row = r0 + e / HH, col = e % HH;
                const float* s = src + row * HH + col;
                float4 a = *(const float4*)s;
                float4 c = *(const float4*)(s + 4);
                __nv_bfloat162 q0 = __floats2bfloat162_rn(a.x, a.y);
                __nv_bfloat162 q1 = __floats2bfloat162_rn(a.z, a.w);
                __nv_bfloat162 q2 = __floats2bfloat162_rn(c.x, c.y);
                __nv_bfloat162 q3 = __floats2bfloat162_rn(c.z, c.w);
                uint4 o;
                o.x = *(unsigned*)&q0; o.y = *(unsigned*)&q1;
                o.z = *(unsigned*)&q2; o.w = *(unsigned*)&q3;
                __nv_bfloat16* d = (m == 2)
                    ? (g_whh1 + row * HH + col)
                    : (g_w2cat + row * (2 * HH) + (m == 1 ? HH : 0) + col);
                *(uint4*)d = o;
            }
        }
    }

    // xproj: own rows r, r+1 (per warp) for all 128 embeddings (f32x2 FMA)
    {
        const int r = b * RPB + w * 2;
        u64 wa[8], wb[8];
        {
            const float4* wra = (const float4*)(Wih1 + (size_t)r * E);
            const float4* wrb = (const float4*)(Wih1 + (size_t)(r + 1) * E);
            #pragma unroll
            for (int i = 0; i < 4; i++) {
                float4 A = __ldg(&wra[lane * 4 + i]);
                float4 B = __ldg(&wrb[lane * 4 + i]);
                wa[2 * i]     = f2pack(A.x, A.y);
                wa[2 * i + 1] = f2pack(A.z, A.w);
                wb[2 * i]     = f2pack(B.x, B.y);
                wb[2 * i + 1] = f2pack(B.z, B.w);
            }
        }
        const float bs0 = __ldg(&bih1[r])     + __ldg(&bhh1[r]);
        const float bs1 = __ldg(&bih1[r + 1]) + __ldg(&bhh1[r + 1]);

        for (int c = 0; c < NV / 16; c++) {
            __syncthreads();
            for (int idx = tid; idx < 16 * (E / 4); idx += NT) {
                int v = idx >> 7, e4 = idx & 127;
                float4 d = __ldg((const float4*)(emb + (size_t)(c * 16 + v) * E) + e4);
                *(float4*)&sMem[v * (E + 8) + e4 * 4] = d;
            }
            __syncthreads();
            #pragma unroll 2
            for (int v = 0; v < 16; v++) {
                const float* ev = &sMem[v * (E + 8) + lane * 16];
                u64 s0 = 0ull, s1 = 0ull;
                #pragma unroll
                for (int i = 0; i < 4; i++) {
                    float4 x = *(const float4*)(ev + 4 * i);
                    u64 x0 = f2pack(x.x, x.y), x1 = f2pack(x.z, x.w);
                    s0 = ffma2(wa[2 * i], x0, s0);
                    s0 = ffma2(wa[2 * i + 1], x1, s0);
                    s1 = ffma2(wb[2 * i], x0, s1);
                    s1 = ffma2(wb[2 * i + 1], x1, s1);
                }
                float a0 = warpsum(f2sum(s0));
                float a1 = warpsum(f2sum(s1));
                if (lane == 0) {
                    g_xproj[(size_t)(c * 16 + v) * G4 + r]     = a0 + bs0;
                    g_xproj[(size_t)(c * 16 + v) * G4 + r + 1] = a1 + bs1;
                }
            }
        }
    }

    grid_sync(b, base + 1);

    // ======== 48-step controller loop ========
    for (int t = 0; t < TT; t++) {
        const int par = t & 1;
        const int rb = t % 3, wb2 = (t + 1) % 3, zb = (t + 2) % 3;

        // ---- loads: logits FIRST (softmax gates the chain) ----
        float lg = 0.f;
        if (t > 0) lg = g_log3[rb][lane * LSTR] + bout[(t - 1) * SS + lane];
        float a0[KU], a1[KU], a2[KU], a3[KU], cc[KU];
        #pragma unroll
        for (int k = 0; k < KU; k++) {
            int u = tid + k * NT;
            sV[HH + u] = g_h2[par][u];          // stage h2(t-1)
            if (t > 0) {
                a0[k] = g_g1[par][u];          a1[k] = g_g1[par][HH + u];
                a2[k] = g_g1[par][2 * HH + u]; a3[k] = g_g1[par][3 * HH + u];
                cc[k] = g_c1[par][u];
            } else {
                a0[k] = a1[k] = a2[k] = a3[k] = cc[k] = 0.f;
            }
        }
        if (tid < SS * UPB) {   // fp32 head slice for this block's units
            int s = tid / UPB, j = tid % UPB;
            sWo[tid] = __ldg(&Wout[((size_t)t * SS + s) * HH + u0 + j]);
        }

        // ---- per-warp redundant softmax/argmax of step t-1 (shfl-only) ----
        int sid;
        if (t > 0) {
            float v = lg;
            float bv = v; int bi = lane;
            #pragma unroll
            for (int o = 16; o; o >>= 1) {
                float ov = __shfl_xor_sync(0xffffffffu, bv, o);
                int   oi = __shfl_xor_sync(0xffffffffu, bi, o);
                if (ov > bv || (ov == bv && oi < bi)) { bv = ov; bi = oi; }
            }
            float e = expf(v - bv), se = e;
            #pragma unroll
            for (int o = 16; o; o >>= 1) se += __shfl_xor_sync(0xffffffffu, se, o);
            float lse = bv + logf(se);
            if (b == 0 && w == 0) out[(t - 1) * SS + lane] = v - lse;
            sid = ((t - 1) & 3) * SS + bi;
        } else {
            sid = *input_id;
        }

        // ---- explicit xproj prefetch (latency hides under dotA) ----
        float xg0[KU], xg1[KU], xg2[KU], xg3[KU];
        {
            const float* xp = g_xproj + (size_t)sid * G4;
            #pragma unroll
            for (int k = 0; k < KU; k++) {
                int u = tid + k * NT;
                xg0[k] = __ldg(&xp[u]);
                xg1[k] = __ldg(&xp[HH + u]);
                xg2[k] = __ldg(&xp[2 * HH + u]);
                xg3[k] = __ldg(&xp[3 * HH + u]);
            }
        }
        __syncthreads();   // h2 staged

        // ---- dotA: W_hh2 @ h2(t-1) (argmax-independent) ----
        float acc[2] = {0.f, 0.f};
        dot2_acc<6>(w2base + HH, 2 * HH, sV + HH, lane, acc);

        // ---- build h1(t) redundantly from prefetched regs; own c1 slice ----
        #pragma unroll
        for (int k = 0; k < KU; k++) {
            int u = tid + k * NT;
            float gi = a0[k] + xg0[k];
            float gf = a1[k] + xg1[k];
            float gg = a2[k] + xg2[k];
            float go = a3[k] + xg3[k];
            float cn = fsigm(gf) * cc[k] + fsigm(gi) * ftanh(gg);
            sV[u] = fsigm(go) * ftanh(cn);
            if (u >= u0 && u < u0 + UPB) g_c1[par ^ 1][u] = cn;
        }
        __syncthreads();

        // ---- FUSED dotB: W_ih2 rows + W_hh1 rows, one pass over h1(t) ----
        float r1[2] = {0.f, 0.f};
        dot2x2_acc<6>(w2base, 2 * HH, w1base, HH, sV, lane, acc, r1);
        acc[0] = warpsum(acc[0]);
        acc[1] = warpsum(acc[1]);
        r1[0]  = warpsum(r1[0]);
        r1[1]  = warpsum(r1[1]);
        if (lane == 0) {
            sG[l0]     = acc[0] + bsum0;
            sG[l0 + 1] = acc[1] + bsum1;
            g_g1[par ^ 1][r1row]     = r1[0];
            g_g1[par ^ 1][r1row + 1] = r1[1];
        }
        __syncthreads();

        // ---- finalize own h2 units + partial logits -> spread atomics ----
        if (w == 0) {
            float hn = 0.f;
            if (lane < UPB) {
                int u = u0 + lane;
                float gi = sG[lane],           gf = sG[UPB + lane];
                float gg = sG[2 * UPB + lane], go = sG[3 * UPB + lane];
                float c  = g_c2[u];
                float cn = fsigm(gf) * c + fsigm(gi) * ftanh(gg);
                g_c2[u]          = cn;
                hn               = fsigm(go) * ftanh(cn);
                g_h2[par ^ 1][u] = hn;
            }
            float p = 0.f;
            #pragma unroll
            for (int j = 0; j < UPB; j++) {
                float hj = __shfl_sync(0xffffffffu, hn, j);
                p = fmaf(sWo[lane * UPB + j], hj, p);
            }
            atomicAdd(&g_log3[wb2][lane * LSTR], p);
        }
        if (b == 0 && w == 1) g_log3[zb][lane * LSTR] = 0.0f;  // recycle buffer

        grid_sync(b, base + 2 + (unsigned)t);
    }

    // epilogue: logp(47) from g_log3[48%3 = 0]
    if (b == 0 && w == 0) {
        float v = g_log3[0][lane * LSTR] + bout[47 * SS + lane];
        float m = v;
        #pragma unroll
        for (int o = 16; o; o >>= 1) m = fmaxf(m, __shfl_xor_sync(0xffffffffu, m, o));
        float e = expf(v - m), se = e;
        #pragma unroll
        for (int o = 16; o; o >>= 1) se += __shfl_xor_sync(0xffffffffu, se, o);
        float lse = m + logf(se);
        out[47 * SS + lane] = v - lse;
    }
}

extern "C" void kernel_launch(void* const* d_in, const int* in_sizes, int n_in,
                              void* d_out, int out_size) {
    const int*   input_id = (const int*)  d_in[0];
    const float* emb      = (const float*)d_in[1];
    const float* W_ih1    = (const float*)d_in[2];
    const float* W_hh1    = (const float*)d_in[3];
    const float* b_ih1    = (const float*)d_in[4];
    const float* b_hh1    = (const float*)d_in[5];
    const float* W_ih2    = (const float*)d_in[6];
    const float* W_hh2    = (const float*)d_in[7];
    const float* b_ih2    = (const float*)d_in[8];
    const float* b_hh2    = (const float*)d_in[9];
    const float* W_out    = (const float*)d_in[10];
    const float* b_out    = (const float*)d_in[11];
    float* out = (float*)d_out;

    nas_all<<<NB, NT>>>(input_id, emb, W_ih1, W_hh1, b_ih1, b_hh1,
                        W_ih2, W_hh2, b_ih2, b_hh2, W_out, b_out, out);
}

// round 14
// speedup vs baseline: 1.2224x; 1.1160x over previous
#include <cuda_runtime.h>
#include <cuda_bf16.h>
#include <math.h>

#define E    512
#define HH   1536
#define G4   6144
#define SS   32
#define TT   48
#define NV   128
#define NB   128       // persistent blocks (1/SM)
#define NT   512       // 16 warps
#define NW   16
#define UPB  12        // h2/c2 units per block
#define RPB  48        // gate rows / whh1 rows per block
#define KU   3         // h-vector elems per thread (HH/NT)
#define LSTR 64        // logit slot stride (256B)
#define FSTR 32        // flag slot stride (128B)
#define WELEM (G4 * HH)

typedef unsigned long long u64;

// ---------------- persistent device state ----------------
__device__ float          g_xproj[NV * G4];            // W_ih1@emb[v] + b_ih1 + b_hh1
__device__ __nv_bfloat16  g_w2cat[(size_t)G4 * 2 * HH];// [W_ih2 | W_hh2] rows of 3072
__device__ __nv_bfloat16  g_whh1[WELEM];
__device__ float          g_c1[2][HH];
__device__ float          g_c2[HH];
__device__ float          g_h2[2][HH];
__device__ float          g_g1[2][G4];                 // W_hh1 @ h1(t), double buffered
__device__ float          g_log3[3][SS * LSTR];        // triple-buffered padded logits
__device__ unsigned       g_flags[NB * FSTR];          // monotonic epochs (never reset)

__device__ __forceinline__ float fsigm(float x) {
    return __fdividef(1.0f, 1.0f + __expf(-x));
}
__device__ __forceinline__ float ftanh(float x) {
    x = fminf(fmaxf(x, -15.0f), 15.0f);
    float e = __expf(2.0f * x);
    return __fdividef(e - 1.0f, e + 1.0f);
}
__device__ __forceinline__ float warpsum(float v) {
    #pragma unroll
    for (int o = 16; o; o >>= 1) v += __shfl_down_sync(0xffffffffu, v, o);
    return v;
}

// ---- packed f32x2 helpers (sm_100+) ----
__device__ __forceinline__ u64 f2pack(float x, float y) {
    u64 r; asm("mov.b64 %0, {%1, %2};" : "=l"(r) : "f"(x), "f"(y)); return r;
}
__device__ __forceinline__ float f2sum(u64 v) {
    float x, y; asm("mov.b64 {%0, %1}, %2;" : "=f"(x), "=f"(y) : "l"(v));
    return x + y;
}
__device__ __forceinline__ u64 bf2f2(unsigned q) {   // bf16x2 -> (f32,f32)
    unsigned lo = q << 16, hi = q & 0xFFFF0000u;
    u64 r; asm("mov.b64 %0, {%1, %2};" : "=l"(r) : "r"(lo), "r"(hi)); return r;
}
__device__ __forceinline__ u64 ffma2(u64 a, u64 b, u64 c) {
    u64 d; asm("fma.rn.f32x2 %0, %1, %2, %3;" : "=l"(d) : "l"(a), "l"(b), "l"(c));
    return d;
}

#define ACC8(acc, q) \
    p = bf2f2(q.x); acc = ffma2(p, vx, acc); \
    p = bf2f2(q.y); acc = ffma2(p, vy, acc); \
    p = bf2f2(q.z); acc = ffma2(p, vz, acc); \
    p = bf2f2(q.w); acc = ffma2(p, vw, acc);

// 3 consecutive rows from one base; one shared vector pass
template<int SEGS>
__device__ __forceinline__ void dot3_acc(const __nv_bfloat16* __restrict__ base,
                                         size_t stride, const float* __restrict__ sv,
                                         int lane, float* acc) {
    u64 p0 = 0ull, p1 = 0ull, p2 = 0ull;
    #pragma unroll
    for (int j = 0; j < SEGS; j++) {
        int seg = lane + 32 * j;
        const float4* v = (const float4*)(sv + seg * 8);
        float4 v0 = v[0], v1 = v[1];
        u64 vx = f2pack(v0.x, v0.y), vy = f2pack(v0.z, v0.w);
        u64 vz = f2pack(v1.x, v1.y), vw = f2pack(v1.z, v1.w);
        uint4 a0 = __ldg((const uint4*)(base) + seg);
        uint4 a1 = __ldg((const uint4*)(base + stride) + seg);
        uint4 a2 = __ldg((const uint4*)(base + 2 * stride) + seg);
        u64 p;
        ACC8(p0, a0)
        ACC8(p1, a1)
        ACC8(p2, a2)
    }
    acc[0] += f2sum(p0);
    acc[1] += f2sum(p1);
    acc[2] += f2sum(p2);
}

// FUSED: 3 rows from baseA + 3 rows from baseB, ONE vector pass
template<int SEGS>
__device__ __forceinline__ void dot3x3_acc(const __nv_bfloat16* __restrict__ baseA,
                                           size_t strideA,
                                           const __nv_bfloat16* __restrict__ baseB,
                                           size_t strideB,
                                           const float* __restrict__ sv, int lane,
                                           float* accA, float* accB) {
    u64 pa0 = 0ull, pa1 = 0ull, pa2 = 0ull;
    u64 pb0 = 0ull, pb1 = 0ull, pb2 = 0ull;
    #pragma unroll
    for (int j = 0; j < SEGS; j++) {
        int seg = lane + 32 * j;
        const float4* v = (const float4*)(sv + seg * 8);
        float4 v0 = v[0], v1 = v[1];
        u64 vx = f2pack(v0.x, v0.y), vy = f2pack(v0.z, v0.w);
        u64 vz = f2pack(v1.x, v1.y), vw = f2pack(v1.z, v1.w);
        uint4 a0 = __ldg((const uint4*)(baseA) + seg);
        uint4 a1 = __ldg((const uint4*)(baseA + strideA) + seg);
        uint4 a2 = __ldg((const uint4*)(baseA + 2 * strideA) + seg);
        uint4 b0 = __ldg((const uint4*)(baseB) + seg);
        uint4 b1 = __ldg((const uint4*)(baseB + strideB) + seg);
        uint4 b2 = __ldg((const uint4*)(baseB + 2 * strideB) + seg);
        u64 p;
        ACC8(pa0, a0)
        ACC8(pa1, a1)
        ACC8(pa2, a2)
        ACC8(pb0, b0)
        ACC8(pb1, b1)
        ACC8(pb2, b2)
    }
    accA[0] += f2sum(pa0);
    accA[1] += f2sum(pa1);
    accA[2] += f2sum(pa2);
    accB[0] += f2sum(pb0);
    accB[1] += f2sum(pb1);
    accB[2] += f2sum(pb2);
}

// symmetric grid barrier: padded per-block flags, first NB threads poll
__device__ __forceinline__ void grid_sync(int b, unsigned ep) {
    __threadfence();
    __syncthreads();
    if (threadIdx.x == 0)
        *(volatile unsigned*)&g_flags[b * FSTR] = ep;
    if (threadIdx.x < NB) {
        volatile unsigned* f = &g_flags[threadIdx.x * FSTR];
        while ((int)(*f - ep) < 0) { __nanosleep(64); }
    }
    __syncthreads();
    __threadfence();
}

// ================== the one and only kernel ==================
__global__ void __launch_bounds__(NT, 1)
nas_all(const int*   __restrict__ input_id,
        const float* __restrict__ emb,
        const float* __restrict__ Wih1,
        const float* __restrict__ Whh1f,
        const float* __restrict__ bih1, const float* __restrict__ bhh1,
        const float* __restrict__ Wih2f,
        const float* __restrict__ Whh2f,
        const float* __restrict__ bih2, const float* __restrict__ bhh2,
        const float* __restrict__ Wout,
        const float* __restrict__ bout,
        float* __restrict__ out) {
    __shared__ __align__(16) float sMem[16 * (E + 8)];   // 33.3 KB; aliased
    float* sV  = sMem;                        // loop: [h1 ; h2] (3072)
    float* sWo = sMem + 2 * HH;               // loop: head slice (384)
    float* sG  = sMem + 2 * HH + SS * UPB;    // loop: gates (48)
    __shared__ unsigned sBase;

    const int tid  = threadIdx.x;
    const int w    = tid >> 5;
    const int lane = tid & 31;
    const int b    = blockIdx.x;
    const int u0   = b * UPB;

    // warp row assignments (3 rows/warp; 3|12 so never crosses a gate boundary)
    const int l0   = 3 * w;                   // 0..45
    const int gate = l0 / UPB;
    const int j0   = l0 % UPB;
    const int grow = gate * HH + u0 + j0;
    const __nv_bfloat16* w2base = g_w2cat + (size_t)grow * (2 * HH);
    const int r1row = b * RPB + l0;
    const __nv_bfloat16* w1base = g_whh1 + (size_t)r1row * HH;
    const float bsum0 = __ldg(&bih2[grow])     + __ldg(&bhh2[grow]);
    const float bsum1 = __ldg(&bih2[grow + 1]) + __ldg(&bhh2[grow + 1]);
    const float bsum2 = __ldg(&bih2[grow + 2]) + __ldg(&bhh2[grow + 2]);

    // ---- epoch base (flags monotonic across graph replays) ----
    if (tid == 0) sBase = g_flags[b * FSTR];
    __syncthreads();
    const unsigned base = sBase;

    // ======== PROLOGUE (distributed by block) ========
    if (tid < UPB) { g_c2[u0 + tid] = 0.f; g_h2[0][u0 + tid] = 0.f; }

    // bf16-convert own RPB rows of W_ih2 / W_hh2 (into concat) and W_hh1
    {
        const size_t r0 = (size_t)b * RPB;
        #pragma unroll
        for (int m = 0; m < 3; m++) {
            const float* src = (m == 0) ? Wih2f : (m == 1) ? Whh2f : Whh1f;
            for (int idx = tid; idx < RPB * HH / 8; idx += NT) {
                size_t e = (size_t)idx * 8;
                size_t row = r0 + e / HH, col = e % HH;
                const float* s = src + row * HH + col;
                float4 a = *(const float4*)s;
                float4 c = *(const float4*)(s + 4);
                __nv_bfloat162 q0 = __floats2bfloat162_rn(a.x, a.y);
                __nv_bfloat162 q1 = __floats2bfloat162_rn(a.z, a.w);
                __nv_bfloat162 q2 = __floats2bfloat162_rn(c.x, c.y);
                __nv_bfloat162 q3 = __floats2bfloat162_rn(c.z, c.w);
                uint4 o;
                o.x = *(unsigned*)&q0; o.y = *(unsigned*)&q1;
                o.z = *(unsigned*)&q2; o.w = *(unsigned*)&q3;
                __nv_bfloat16* d = (m == 2)
                    ? (g_whh1 + row * HH + col)
                    : (g_w2cat + row * (2 * HH) + (m == 1 ? HH : 0) + col);
                *(uint4*)d = o;
            }
        }
    }

    // xproj: own rows r, r+1, r+2 (per warp) for all 128 embeddings
    {
        const int r = b * RPB + w * 3;
        u64 wa[8], wb[8], wc[8];
        {
            const float4* wra = (const float4*)(Wih1 + (size_t)r * E);
            const float4* wrb = (const float4*)(Wih1 + (size_t)(r + 1) * E);
            const float4* wrc = (const float4*)(Wih1 + (size_t)(r + 2) * E);
            #pragma unroll
            for (int i = 0; i < 4; i++) {
                float4 A = __ldg(&wra[lane * 4 + i]);
                float4 B = __ldg(&wrb[lane * 4 + i]);
                float4 C = __ldg(&wrc[lane * 4 + i]);
                wa[2 * i] = f2pack(A.x, A.y); wa[2 * i + 1] = f2pack(A.z, A.w);
                wb[2 * i] = f2pack(B.x, B.y); wb[2 * i + 1] = f2pack(B.z, B.w);
                wc[2 * i] = f2pack(C.x, C.y); wc[2 * i + 1] = f2pack(C.z, C.w);
            }
        }
        const float bs0 = __ldg(&bih1[r])     + __ldg(&bhh1[r]);
        const float bs1 = __ldg(&bih1[r + 1]) + __ldg(&bhh1[r + 1]);
        const float bs2 = __ldg(&bih1[r + 2]) + __ldg(&bhh1[r + 2]);

        for (int c = 0; c < NV / 16; c++) {
            __syncthreads();
            for (int idx = tid; idx < 16 * (E / 4); idx += NT) {
                int v = idx >> 7, e4 = idx & 127;
                float4 d = __ldg((const float4*)(emb + (size_t)(c * 16 + v) * E) + e4);
                *(float4*)&sMem[v * (E + 8) + e4 * 4] = d;
            }
            __syncthreads();
            #pragma unroll 2
            for (int v = 0; v < 16; v++) {
                const float* ev = &sMem[v * (E + 8) + lane * 16];
                u64 s0 = 0ull, s1 = 0ull, s2 = 0ull;
                #pragma unroll
                for (int i = 0; i < 4; i++) {
                    float4 x = *(const float4*)(ev + 4 * i);
                    u64 x0 = f2pack(x.x, x.y), x1 = f2pack(x.z, x.w);
                    s0 = ffma2(wa[2 * i], x0, s0);
                    s0 = ffma2(wa[2 * i + 1], x1, s0);
                    s1 = ffma2(wb[2 * i], x0, s1);
                    s1 = ffma2(wb[2 * i + 1], x1, s1);
                    s2 = ffma2(wc[2 * i], x0, s2);
                    s2 = ffma2(wc[2 * i + 1], x1, s2);
                }
                float a0 = warpsum(f2sum(s0));
                float a1 = warpsum(f2sum(s1));
                float a2 = warpsum(f2sum(s2));
                if (lane == 0) {
                    size_t o = (size_t)(c * 16 + v) * G4 + r;
                    g_xproj[o]     = a0 + bs0;
                    g_xproj[o + 1] = a1 + bs1;
                    g_xproj[o + 2] = a2 + bs2;
                }
            }
        }
    }

    grid_sync(b, base + 1);

    // ======== 48-step controller loop ========
    for (int t = 0; t < TT; t++) {
        const int par = t & 1;
        const int rb = t % 3, wb2 = (t + 1) % 3, zb = (t + 2) % 3;

        // ---- loads: logits FIRST (softmax gates the chain) ----
        float lg = 0.f;
        if (t > 0) lg = g_log3[rb][lane * LSTR] + bout[(t - 1) * SS + lane];
        float a0[KU], a1[KU], a2[KU], a3[KU], cc[KU];
        #pragma unroll
        for (int k = 0; k < KU; k++) {
            int u = tid + k * NT;
            sV[HH + u] = g_h2[par][u];          // stage h2(t-1)
            if (t > 0) {
                a0[k] = g_g1[par][u];          a1[k] = g_g1[par][HH + u];
                a2[k] = g_g1[par][2 * HH + u]; a3[k] = g_g1[par][3 * HH + u];
                cc[k] = g_c1[par][u];
            } else {
                a0[k] = a1[k] = a2[k] = a3[k] = cc[k] = 0.f;
            }
        }
        if (tid < SS * UPB) {   // fp32 head slice for this block's units
            int s = tid / UPB, j = tid % UPB;
            sWo[tid] = __ldg(&Wout[((size_t)t * SS + s) * HH + u0 + j]);
        }

        // ---- per-warp redundant softmax/argmax of step t-1 (shfl-only) ----
        int sid;
        if (t > 0) {
            float v = lg;
            float bv = v; int bi = lane;
            #pragma unroll
            for (int o = 16; o; o >>= 1) {
                float ov = __shfl_xor_sync(0xffffffffu, bv, o);
                int   oi = __shfl_xor_sync(0xffffffffu, bi, o);
                if (ov > bv || (ov == bv && oi < bi)) { bv = ov; bi = oi; }
            }
            float e = expf(v - bv), se = e;
            #pragma unroll
            for (int o = 16; o; o >>= 1) se += __shfl_xor_sync(0xffffffffu, se, o);
            float lse = bv + logf(se);
            if (b == 0 && w == 0) out[(t - 1) * SS + lane] = v - lse;
            sid = ((t - 1) & 3) * SS + bi;
        } else {
            sid = *input_id;
        }

        // ---- explicit xproj prefetch (latency hides under dotA) ----
        float xg0[KU], xg1[KU], xg2[KU], xg3[KU];
        {
            const float* xp = g_xproj + (size_t)sid * G4;
            #pragma unroll
            for (int k = 0; k < KU; k++) {
                int u = tid + k * NT;
                xg0[k] = __ldg(&xp[u]);
                xg1[k] = __ldg(&xp[HH + u]);
                xg2[k] = __ldg(&xp[2 * HH + u]);
                xg3[k] = __ldg(&xp[3 * HH + u]);
            }
        }
        __syncthreads();   // h2 staged

        // ---- dotA: W_hh2 @ h2(t-1) (argmax-independent) ----
        float acc[3] = {0.f, 0.f, 0.f};
        dot3_acc<6>(w2base + HH, 2 * HH, sV + HH, lane, acc);

        // ---- build h1(t) redundantly from prefetched regs; own c1 slice ----
        #pragma unroll
        for (int k = 0; k < KU; k++) {
            int u = tid + k * NT;
            float gi = a0[k] + xg0[k];
            float gf = a1[k] + xg1[k];
            float gg = a2[k] + xg2[k];
            float go = a3[k] + xg3[k];
            float cn = fsigm(gf) * cc[k] + fsigm(gi) * ftanh(gg);
            sV[u] = fsigm(go) * ftanh(cn);
            if (u >= u0 && u < u0 + UPB) g_c1[par ^ 1][u] = cn;
        }
        __syncthreads();

        // ---- FUSED dotB: W_ih2 rows + W_hh1 rows, one pass over h1(t) ----
        float r1[3] = {0.f, 0.f, 0.f};
        dot3x3_acc<6>(w2base, 2 * HH, w1base, HH, sV, lane, acc, r1);
        acc[0] = warpsum(acc[0]);
        acc[1] = warpsum(acc[1]);
        acc[2] = warpsum(acc[2]);
        r1[0]  = warpsum(r1[0]);
        r1[1]  = warpsum(r1[1]);
        r1[2]  = warpsum(r1[2]);
        if (lane == 0) {
            sG[l0]     = acc[0] + bsum0;
            sG[l0 + 1] = acc[1] + bsum1;
            sG[l0 + 2] = acc[2] + bsum2;
            g_g1[par ^ 1][r1row]     = r1[0];
            g_g1[par ^ 1][r1row + 1] = r1[1];
            g_g1[par ^ 1][r1row + 2] = r1[2];
        }
        __syncthreads();

        // ---- finalize own h2 units + partial logits -> spread atomics ----
        if (w == 0) {
            float hn = 0.f;
            if (lane < UPB) {
                int u = u0 + lane;
                float gi = sG[lane],           gf = sG[UPB + lane];
                float gg = sG[2 * UPB + lane], go = sG[3 * UPB + lane];
                float c  = g_c2[u];
                float cn = fsigm(gf) * c + fsigm(gi) * ftanh(gg);
                g_c2[u]          = cn;
                hn               = fsigm(go) * ftanh(cn);
                g_h2[par ^ 1][u] = hn;
            }
            float p = 0.f;
            #pragma unroll
            for (int j = 0; j < UPB; j++) {
                float hj = __shfl_sync(0xffffffffu, hn, j);
                p = fmaf(sWo[lane * UPB + j], hj, p);
            }
            atomicAdd(&g_log3[wb2][lane * LSTR], p);
        }
        if (b == 0 && w == 1) g_log3[zb][lane * LSTR] = 0.0f;  // recycle buffer

        grid_sync(b, base + 2 + (unsigned)t);
    }

    // epilogue: logp(47) from g_log3[48%3 = 0]
    if (b == 0 && w == 0) {
        float v = g_log3[0][lane * LSTR] + bout[47 * SS + lane];
        float m = v;
        #pragma unroll
        for (int o = 16; o; o >>= 1) m = fmaxf(m, __shfl_xor_sync(0xffffffffu, m, o));
        float e = expf(v - m), se = e;
        #pragma unroll
        for (int o = 16; o; o >>= 1) se += __shfl_xor_sync(0xffffffffu, se, o);
        float lse = m + logf(se);
        out[47 * SS + lane] = v - lse;
    }
}

extern "C" void kernel_launch(void* const* d_in, const int* in_sizes, int n_in,
                              void* d_out, int out_size) {
    const int*   input_id = (const int*)  d_in[0];
    const float* emb      = (const float*)d_in[1];
    const float* W_ih1    = (const float*)d_in[2];
    const float* W_hh1    = (const float*)d_in[3];
    const float* b_ih1    = (const float*)d_in[4];
    const float* b_hh1    = (const float*)d_in[5];
    const float* W_ih2    = (const float*)d_in[6];
    const float* W_hh2    = (const float*)d_in[7];
    const float* b_ih2    = (const float*)d_in[8];
    const float* b_hh2    = (const float*)d_in[9];
    const float* W_out    = (const float*)d_in[10];
    const float* b_out    = (const float*)d_in[11];
    float* out = (float*)d_out;

    nas_all<<<NB, NT>>>(input_id, emb, W_ih1, W_hh1, b_ih1, b_hh1,
                        W_ih2, W_hh2, b_ih2, b_hh2, W_out, b_out, out);
}